// round 14
// baseline (speedup 1.0000x reference)
#include <cuda_runtime.h>
#include <cuda_fp16.h>
#include <math.h>
#include <stdint.h>

#define SEQ   2048
#define HID   3584
#define NH    28
#define NKV   4
#define HD    128
#define KVDIM 512   // NKV * HD

// ---------------- scratch (no allocations allowed) ----------------
__device__ float  g_q[SEQ * HID];
__device__ float  g_k[SEQ * KVDIM];
__device__ __half g_qh[SEQ * HID];
__device__ __half g_kh[SEQ * KVDIM];
__device__ __half g_vh[SEQ * KVDIM];
__device__ __half g_ctx_h[SEQ * HID];
__device__ __half g_hs_h[SEQ * HID];
__device__ __half g_wq_h[(size_t)HID * HID];
__device__ __half g_wk_h[(size_t)KVDIM * HID];
__device__ __half g_wv_h[(size_t)KVDIM * HID];
__device__ __half g_wo_h[(size_t)HID * HID];
__device__ float  g_cos[SEQ * 64];
__device__ float  g_sin[SEQ * 64];

// ---------------- helpers ----------------
__device__ __forceinline__ uint32_t smem_u32(const void* p) {
    uint32_t a;
    asm("{ .reg .u64 t; cvta.to.shared.u64 t, %1; cvt.u32.u64 %0, t; }" : "=r"(a) : "l"(p));
    return a;
}

__device__ __forceinline__ uint32_t h2_as_u32(__half2 h) {
    return *reinterpret_cast<uint32_t*>(&h);
}

__device__ __forceinline__ void mma_f16(float* c, const uint32_t* a, const uint32_t* b) {
    asm volatile(
        "mma.sync.aligned.m16n8k16.row.col.f32.f16.f16.f32 "
        "{%0,%1,%2,%3}, {%4,%5,%6,%7}, {%8,%9}, {%0,%1,%2,%3};\n"
        : "+f"(c[0]), "+f"(c[1]), "+f"(c[2]), "+f"(c[3])
        : "r"(a[0]), "r"(a[1]), "r"(a[2]), "r"(a[3]), "r"(b[0]), "r"(b[1]));
}

__device__ __forceinline__ void ldm_x4(uint32_t* r, uint32_t addr) {
    asm volatile("ldmatrix.sync.aligned.m8n8.x4.shared.b16 {%0,%1,%2,%3}, [%4];"
                 : "=r"(r[0]), "=r"(r[1]), "=r"(r[2]), "=r"(r[3]) : "r"(addr));
}

__device__ __forceinline__ void ldm_x4_t(uint32_t* r, uint32_t addr) {
    asm volatile("ldmatrix.sync.aligned.m8n8.x4.trans.shared.b16 {%0,%1,%2,%3}, [%4];"
                 : "=r"(r[0]), "=r"(r[1]), "=r"(r[2]), "=r"(r[3]) : "r"(addr));
}

// ---------------- fp32 -> fp16 conversion, 4 float4/thread (MLP=4) --------
// n4 MUST be a multiple of 1024 (all call sites are).
__global__ void cvt_half(const float* __restrict__ in, __half* __restrict__ out, int n4) {
    const int i0 = blockIdx.x * 1024 + threadIdx.x;
    float4 v[4];
    #pragma unroll
    for (int j = 0; j < 4; j++) v[j] = ((const float4*)in)[i0 + j * 256];
    #pragma unroll
    for (int j = 0; j < 4; j++) {
        const int i = i0 + j * 256;
        ((__half2*)out)[i * 2 + 0] = __floats2half2_rn(v[j].x, v[j].y);
        ((__half2*)out)[i * 2 + 1] = __floats2half2_rn(v[j].z, v[j].w);
    }
}

// ---------------- FP16 GEMM body: BK=64, 3-stage cp.async, 1 sync/iter -----
// Row stride 72 halves (144B = 9x16B, odd -> ldmatrix conflict-free).
#define GSTRIDE 72
#define GTILE_H (128 * GSTRIDE)   // 9216 halves per stage
#define GSTAGES 3
#define GEMM_SMEM_BYTES (2 * GSTAGES * GTILE_H * 2)   // 110592 B (<114KB, 2 CTAs/SM)

__device__ __forceinline__ void gemm_body(
    const __half* __restrict__ A, const __half* __restrict__ W,
    const float* __restrict__ bias, float* __restrict__ Cf, __half* __restrict__ Ch,
    int N, int K, int bm, int bn, __half* As, __half* Bs)
{
    const int tid  = threadIdx.x;
    const int lane = tid & 31;
    const int wid  = tid >> 5;

    const int warp_m = (wid >> 1) * 32;
    const int warp_n = (wid & 1) * 64;

    const uint32_t sbA = smem_u32(As);
    const uint32_t sbB = smem_u32(Bs);

    // cp.async mapping: 128 rows x 8 chunks (16B) per operand per stage; 4/thread
    int lrow[4], lch[4];
    #pragma unroll
    for (int p = 0; p < 4; p++) {
        int f = tid + p * 256;
        lrow[p] = f >> 3;
        lch[p]  = f & 7;
    }

    const int nt = K / 64;

    // prologue: stages 0 and 1
    #pragma unroll
    for (int st = 0; st < 2; st++) {
        const uint32_t ab = sbA + (uint32_t)st * (GTILE_H * 2);
        const uint32_t bb = sbB + (uint32_t)st * (GTILE_H * 2);
        #pragma unroll
        for (int p = 0; p < 4; p++) {
            uint32_t so = (uint32_t)lrow[p] * 144u + (uint32_t)lch[p] * 16u;
            const __half* ga = A + (size_t)(bm + lrow[p]) * K + (size_t)st * 64 + lch[p] * 8;
            const __half* gb = W + (size_t)(bn + lrow[p]) * K + (size_t)st * 64 + lch[p] * 8;
            asm volatile("cp.async.cg.shared.global [%0], [%1], 16;" :: "r"(ab + so), "l"(ga) : "memory");
            asm volatile("cp.async.cg.shared.global [%0], [%1], 16;" :: "r"(bb + so), "l"(gb) : "memory");
        }
        asm volatile("cp.async.commit_group;" ::: "memory");
    }

    float acc[2][8][4];
    #pragma unroll
    for (int mi = 0; mi < 2; mi++)
        #pragma unroll
        for (int ni = 0; ni < 8; ni++)
            #pragma unroll
            for (int j = 0; j < 4; j++) acc[mi][ni][j] = 0.f;

    const int lg = lane >> 3;
    const int lr = lane & 7;

    int cur = 0, nxt = 2;
    for (int i = 0; i < nt; i++) {
        if (i < nt - 1) asm volatile("cp.async.wait_group 1;" ::: "memory");   // chunk i resident
        else            asm volatile("cp.async.wait_group 0;" ::: "memory");
        __syncthreads();   // prior reads of buffer nxt (last used at iter i-1) done

        // issue chunk i+2 into buffer (i+2)%3 (overlaps compute below)
        if (i + 2 < nt) {
            const uint32_t ab = sbA + (uint32_t)nxt * (GTILE_H * 2);
            const uint32_t bb = sbB + (uint32_t)nxt * (GTILE_H * 2);
            #pragma unroll
            for (int p = 0; p < 4; p++) {
                uint32_t so = (uint32_t)lrow[p] * 144u + (uint32_t)lch[p] * 16u;
                const __half* ga = A + (size_t)(bm + lrow[p]) * K + (size_t)(i + 2) * 64 + lch[p] * 8;
                const __half* gb = W + (size_t)(bn + lrow[p]) * K + (size_t)(i + 2) * 64 + lch[p] * 8;
                asm volatile("cp.async.cg.shared.global [%0], [%1], 16;" :: "r"(ab + so), "l"(ga) : "memory");
                asm volatile("cp.async.cg.shared.global [%0], [%1], 16;" :: "r"(bb + so), "l"(gb) : "memory");
            }
            asm volatile("cp.async.commit_group;" ::: "memory");
        }

        const uint32_t abuf = sbA + (uint32_t)cur * (GTILE_H * 2);
        const uint32_t bbuf = sbB + (uint32_t)cur * (GTILE_H * 2);

        #pragma unroll
        for (int s = 0; s < 4; s++) {          // 4 k16-steps per 64-half chunk
            uint32_t a[2][4], bq[4][4];
            #pragma unroll
            for (int mi = 0; mi < 2; mi++) {
                int row = warp_m + mi * 16 + lr + (lg & 1) * 8;
                int ch  = s * 2 + (lg >> 1);
                ldm_x4(a[mi], abuf + (uint32_t)row * 144u + (uint32_t)ch * 16u);
            }
            #pragma unroll
            for (int pr = 0; pr < 4; pr++) {
                int row = warp_n + pr * 16 + lr + (lg >> 1) * 8;
                int ch  = s * 2 + (lg & 1);
                ldm_x4(bq[pr], bbuf + (uint32_t)row * 144u + (uint32_t)ch * 16u);
            }
            #pragma unroll
            for (int mi = 0; mi < 2; mi++)
                #pragma unroll
                for (int pr = 0; pr < 4; pr++) {
                    mma_f16(acc[mi][pr * 2 + 0], a[mi], &bq[pr][0]);
                    mma_f16(acc[mi][pr * 2 + 1], a[mi], &bq[pr][2]);
                }
        }

        cur = (cur + 1 == GSTAGES) ? 0 : cur + 1;
        nxt = (nxt + 1 == GSTAGES) ? 0 : nxt + 1;
    }

    #pragma unroll
    for (int ni = 0; ni < 8; ni++) {
        const int col = bn + warp_n + ni * 8 + (lane & 3) * 2;
        float b0 = 0.f, b1 = 0.f;
        if (bias) { b0 = bias[col]; b1 = bias[col + 1]; }
        #pragma unroll
        for (int mi = 0; mi < 2; mi++) {
            const int row = bm + warp_m + mi * 16 + (lane >> 2);
            if (Ch) {
                *(__half2*)(Ch + (size_t)row * N + col) =
                    __floats2half2_rn(acc[mi][ni][0] + b0, acc[mi][ni][1] + b1);
                *(__half2*)(Ch + (size_t)(row + 8) * N + col) =
                    __floats2half2_rn(acc[mi][ni][2] + b0, acc[mi][ni][3] + b1);
            } else {
                float2 v0 = make_float2(acc[mi][ni][0] + b0, acc[mi][ni][1] + b1);
                float2 v1 = make_float2(acc[mi][ni][2] + b0, acc[mi][ni][3] + b1);
                *(float2*)(Cf + (size_t)row * N + col) = v0;
                *(float2*)(Cf + (size_t)(row + 8) * N + col) = v1;
            }
        }
    }
}

// generic GEMM (O-projection, fp32 out)
__global__ __launch_bounds__(256, 2) void gemm_f16(
    const __half* __restrict__ A, const __half* __restrict__ W,
    const float* __restrict__ bias, float* __restrict__ C,
    int M, int N, int K)
{
    extern __shared__ __align__(16) __half gsh[];
    gemm_body(A, W, bias, C, (__half*)0, N, K, blockIdx.y * 128, blockIdx.x * 128,
              gsh, gsh + GSTAGES * GTILE_H);
}

// fused Q/K/V projection: 36 block-cols; V written directly as fp16
__global__ __launch_bounds__(256, 2) void gemm_qkv(
    const __half* __restrict__ A,
    const __half* __restrict__ wq, const __half* __restrict__ wk, const __half* __restrict__ wv,
    const float* __restrict__ bq, const float* __restrict__ bk, const float* __restrict__ bv,
    float* __restrict__ q, float* __restrict__ k, __half* __restrict__ vh)
{
    extern __shared__ __align__(16) __half gsh[];
    const int bx = blockIdx.x;
    const __half* W; const float* bias; float* Cf; __half* Ch; int N, bn;
    if (bx < HID / 128) {
        W = wq; bias = bq; Cf = q; Ch = 0; N = HID; bn = bx * 128;
    } else if (bx < HID / 128 + KVDIM / 128) {
        W = wk; bias = bk; Cf = k; Ch = 0; N = KVDIM; bn = (bx - HID / 128) * 128;
    } else {
        W = wv; bias = bv; Cf = 0; Ch = vh; N = KVDIM; bn = (bx - HID / 128 - KVDIM / 128) * 128;
    }
    gemm_body(A, W, bias, Cf, Ch, N, HID, blockIdx.y * 128, bn,
              gsh, gsh + GSTAGES * GTILE_H);
}

// ---------------- RoPE tables + apply (vectorized, 4 dims/thread) ----------
__global__ void rope_tables(float* __restrict__ cosd, float* __restrict__ sind) {
    int i = blockIdx.x * blockDim.x + threadIdx.x;
    int half = i & 63;
    int s = i >> 6;
    double inv = exp(-log(1.0e6) * (double)(2 * half) / 128.0);
    double ang = (double)s * inv;
    cosd[i] = (float)cos(ang);
    sind[i] = (float)sin(ang);
}

// one thread handles 4 consecutive dims of one (s, h) row: float4 in, half2 out
__global__ void rope_apply(const float* __restrict__ x, __half* __restrict__ xh,
                           const float* __restrict__ cosd, const float* __restrict__ sind,
                           int nheads)
{
    int idx = blockIdx.x * blockDim.x + threadIdx.x;   // SEQ*nheads*16 threads
    int d4 = (idx & 15) << 2;           // 0,4,...,60
    int h  = (idx >> 4) % nheads;
    int s  = idx / (16 * nheads);

    float4 c  = *(const float4*)&cosd[s * 64 + d4];
    float4 si = *(const float4*)&sind[s * 64 + d4];

    const float* base = x + (size_t)s * nheads * HD + h * HD;
    __half* baseh = xh + (size_t)s * nheads * HD + h * HD;
    float4 x1 = *(const float4*)&base[d4];
    float4 x2 = *(const float4*)&base[d4 + 64];

    *(__half2*)&baseh[d4]          = __floats2half2_rn(x1.x * c.x - x2.x * si.x,
                                                       x1.y * c.y - x2.y * si.y);
    *(__half2*)&baseh[d4 + 2]      = __floats2half2_rn(x1.z * c.z - x2.z * si.z,
                                                       x1.w * c.w - x2.w * si.w);
    *(__half2*)&baseh[d4 + 64]     = __floats2half2_rn(x2.x * c.x + x1.x * si.x,
                                                       x2.y * c.y + x1.y * si.y);
    *(__half2*)&baseh[d4 + 64 + 2] = __floats2half2_rn(x2.z * c.z + x1.z * si.z,
                                                       x2.w * c.w + x1.w * si.w);
}

// ---------------- Flash attention (FA2): 128q block, warp = 16q x 64k ------
// 1-D grid in strict LPT order. Softmax in log2 domain (exp2f, scale folded).
#define AQ_STR 136
#define ATTN_SMEM_BYTES ((128 * AQ_STR + 4 * 64 * AQ_STR) * 2)

__global__ __launch_bounds__(256, 2) void attn_f16(
    const __half* __restrict__ q, const __half* __restrict__ k,
    const __half* __restrict__ v, __half* __restrict__ ctx)
{
    extern __shared__ __align__(16) char smraw[];
    __half* Qh = (__half*)smraw;                    // [128][136]
    __half* Kh = Qh + 128 * AQ_STR;                 // [2][64][136]
    __half* Vh = Kh + 2 * 64 * AQ_STR;              // [2][64][136]

    const int b   = blockIdx.x;                     // 0..447, LPT order
    const int qt  = (SEQ / 128 - 1) - (b / NH);     // heaviest first across ALL heads
    const int h   = b % NH;
    const int kvh = h / 7;
    const int tid  = threadIdx.x;
    const int lane = tid & 31;
    const int wid  = tid >> 5;

    const int wm = wid * 16;                        // warp's q-row base
    const int lg = lane >> 3;
    const int lr = lane & 7;
    const int qr = lane >> 2;                       // row-in-slab (0..7)
    const int qc = lane & 3;

    const uint32_t sQ = smem_u32(Qh);
    const uint32_t sK = smem_u32(Kh);
    const uint32_t sV = smem_u32(Vh);

    // K/V cp.async mapping: 64 rows x 128 cols = 1024 uint4; 4 per thread
    int trow[4], tcol[4];
    #pragma unroll
    for (int i = 0; i < 4; i++) {
        int f = tid + i * 256;
        trow[i] = f >> 4;
        tcol[i] = (f & 15) * 8;
    }

    const int nkt = 2 * qt + 2;

    // prologue: cp.async tile 0 into stage 0
    {
        const __half* kb = k + kvh * HD;
        const __half* vb = v + kvh * HD;
        #pragma unroll
        for (int i = 0; i < 4; i++) {
            uint32_t so = (uint32_t)trow[i] * (AQ_STR * 2) + (uint32_t)tcol[i] * 2;
            asm volatile("cp.async.cg.shared.global [%0], [%1], 16;"
                         :: "r"(sK + so), "l"(kb + (size_t)trow[i] * KVDIM + tcol[i]) : "memory");
            asm volatile("cp.async.cg.shared.global [%0], [%1], 16;"
                         :: "r"(sV + so), "l"(vb + (size_t)trow[i] * KVDIM + tcol[i]) : "memory");
        }
        asm volatile("cp.async.commit_group;" ::: "memory");
    }

    // load Q tile (128 rows)
    {
        const __half* qbase = q + (size_t)(qt * 128) * HID + h * HD;
        #pragma unroll
        for (int i = 0; i < 8; i++) {
            int f = tid + i * 256;
            int r = f >> 4;
            int c = (f & 15) * 8;
            *(uint4*)&Qh[r * AQ_STR + c] = *(const uint4*)(qbase + (size_t)r * HID + c);
        }
    }

    float out[16][4];
    #pragma unroll
    for (int ni = 0; ni < 16; ni++)
        #pragma unroll
        for (int j = 0; j < 4; j++) out[ni][j] = 0.f;
    float m0 = -INFINITY, m1 = -INFINITY, l0 = 0.f, l1 = 0.f;

    // scale * log2(e): softmax runs in log2 domain, exp2f = bare MUFU.EX2
    const float scale_l2e = 0.12751741958f;         // (1/sqrt(128)) * log2(e)
    const float mask_l2e  = -1.4426950e9f;          // -1e9 * log2(e)

    for (int kt = 0; kt < nkt; kt++) {
        asm volatile("cp.async.wait_group 0;" ::: "memory");
        __syncthreads();

        // issue next tile into the other stage (overlaps compute below)
        if (kt + 1 < nkt) {
            const uint32_t stoff = (uint32_t)((kt + 1) & 1) * (64 * AQ_STR * 2);
            const __half* kb = k + (size_t)((kt + 1) * 64) * KVDIM + kvh * HD;
            const __half* vb = v + (size_t)((kt + 1) * 64) * KVDIM + kvh * HD;
            #pragma unroll
            for (int i = 0; i < 4; i++) {
                uint32_t so = (uint32_t)trow[i] * (AQ_STR * 2) + (uint32_t)tcol[i] * 2 + stoff;
                asm volatile("cp.async.cg.shared.global [%0], [%1], 16;"
                             :: "r"(sK + so), "l"(kb + (size_t)trow[i] * KVDIM + tcol[i]) : "memory");
                asm volatile("cp.async.cg.shared.global [%0], [%1], 16;"
                             :: "r"(sV + so), "l"(vb + (size_t)trow[i] * KVDIM + tcol[i]) : "memory");
            }
            asm volatile("cp.async.commit_group;" ::: "memory");
        }

        const uint32_t kbuf = sK + (uint32_t)(kt & 1) * (64 * AQ_STR * 2);
        const uint32_t vbuf = sV + (uint32_t)(kt & 1) * (64 * AQ_STR * 2);

        // ---- S = Q @ K^T : sfrag[8] covers 64 keys ----
        float sfrag[8][4];
        #pragma unroll
        for (int ni = 0; ni < 8; ni++)
            #pragma unroll
            for (int j = 0; j < 4; j++) sfrag[ni][j] = 0.f;

        #pragma unroll
        for (int s = 0; s < 8; s++) {
            uint32_t a[4];
            {
                int row = wm + lr + (lg & 1) * 8;
                int ch  = s * 2 + (lg >> 1);
                ldm_x4(a, sQ + ((uint32_t)row * AQ_STR + (uint32_t)ch * 8) * 2u);
            }
            #pragma unroll
            for (int pr = 0; pr < 4; pr++) {
                uint32_t bq[4];
                int row = pr * 16 + lr + (lg >> 1) * 8;
                int ch  = s * 2 + (lg & 1);
                ldm_x4(bq, kbuf + ((uint32_t)row * AQ_STR + (uint32_t)ch * 8) * 2u);
                mma_f16(sfrag[pr * 2 + 0], a, &bq[0]);
                mma_f16(sfrag[pr * 2 + 1], a, &bq[2]);
            }
        }

        // ---- scale (log2 domain) + causal mask ----
        const bool diag = (kt >= 2 * qt);
        const int qr0 = qt * 128 + wm + qr;
        #pragma unroll
        for (int ni = 0; ni < 8; ni++) {
            const int kc = kt * 64 + ni * 8 + qc * 2;
            sfrag[ni][0] *= scale_l2e; sfrag[ni][1] *= scale_l2e;
            sfrag[ni][2] *= scale_l2e; sfrag[ni][3] *= scale_l2e;
            if (diag) {
                if (kc > qr0)         sfrag[ni][0] += mask_l2e;
                if (kc + 1 > qr0)     sfrag[ni][1] += mask_l2e;
                if (kc > qr0 + 8)     sfrag[ni][2] += mask_l2e;
                if (kc + 1 > qr0 + 8) sfrag[ni][3] += mask_l2e;
            }
        }

        // ---- row max (quad reduce) + rescale ----
        float mx0 = m0, mx1 = m1;
        #pragma unroll
        for (int ni = 0; ni < 8; ni++) {
            mx0 = fmaxf(mx0, fmaxf(sfrag[ni][0], sfrag[ni][1]));
            mx1 = fmaxf(mx1, fmaxf(sfrag[ni][2], sfrag[ni][3]));
        }
        mx0 = fmaxf(mx0, __shfl_xor_sync(0xffffffffu, mx0, 1));
        mx0 = fmaxf(mx0, __shfl_xor_sync(0xffffffffu, mx0, 2));
        mx1 = fmaxf(mx1, __shfl_xor_sync(0xffffffffu, mx1, 1));
        mx1 = fmaxf(mx1, __shfl_xor_sync(0xffffffffu, mx1, 2));
        const float al0 = exp2f(m0 - mx0);
        const float al1 = exp2f(m1 - mx1);
        m0 = mx0; m1 = mx1;
        #pragma unroll
        for (int ni = 0; ni < 16; ni++) {
            out[ni][0] *= al0; out[ni][1] *= al0;
            out[ni][2] *= al1; out[ni][3] *= al1;
        }

        // ---- exp2 -> P frags; PV interleaved per k16-step ----
        float sum0 = 0.f, sum1 = 0.f;
        #pragma unroll
        for (int s = 0; s < 4; s++) {
            float p00 = exp2f(sfrag[2*s][0]   - mx0), p01 = exp2f(sfrag[2*s][1]   - mx0);
            float p10 = exp2f(sfrag[2*s][2]   - mx1), p11 = exp2f(sfrag[2*s][3]   - mx1);
            float p20 = exp2f(sfrag[2*s+1][0] - mx0), p21 = exp2f(sfrag[2*s+1][1] - mx0);
            float p30 = exp2f(sfrag[2*s+1][2] - mx1), p31 = exp2f(sfrag[2*s+1][3] - mx1);
            sum0 += p00 + p01 + p20 + p21;
            sum1 += p10 + p11 + p30 + p31;
            uint32_t pf[4];
            pf[0] = h2_as_u32(__floats2half2_rn(p00, p01));
            pf[1] = h2_as_u32(__floats2half2_rn(p10, p11));
            pf[2] = h2_as_u32(__floats2half2_rn(p20, p21));
            pf[3] = h2_as_u32(__floats2half2_rn(p30, p31));
            #pragma unroll
            for (int nb = 0; nb < 8; nb++) {
                uint32_t bv[4];
                int row = s * 16 + (lg & 1) * 8 + lr;        // key row
                int col = nb * 16 + (lg >> 1) * 8;           // d col
                ldm_x4_t(bv, vbuf + ((uint32_t)row * AQ_STR + (uint32_t)col) * 2u);
                mma_f16(out[nb * 2 + 0], pf, &bv[0]);
                mma_f16(out[nb * 2 + 1], pf, &bv[2]);
            }
        }
        sum0 += __shfl_xor_sync(0xffffffffu, sum0, 1);
        sum0 += __shfl_xor_sync(0xffffffffu, sum0, 2);
        sum1 += __shfl_xor_sync(0xffffffffu, sum1, 1);
        sum1 += __shfl_xor_sync(0xffffffffu, sum1, 2);
        l0 = l0 * al0 + sum0;
        l1 = l1 * al1 + sum1;
    }

    // ---- epilogue ----
    {
        const float inv0 = 1.f / l0;
        const float inv1 = 1.f / l1;
        const int row0 = qt * 128 + wm + qr;
        #pragma unroll
        for (int ni = 0; ni < 16; ni++) {
            const int col = h * HD + ni * 8 + qc * 2;
            *(__half2*)(ctx + (size_t)row0 * HID + col) =
                __floats2half2_rn(out[ni][0] * inv0, out[ni][1] * inv0);
            *(__half2*)(ctx + (size_t)(row0 + 8) * HID + col) =
                __floats2half2_rn(out[ni][2] * inv1, out[ni][3] * inv1);
        }
    }
}

// ---------------- host launcher ----------------
extern "C" void kernel_launch(void* const* d_in, const int* in_sizes, int n_in,
                              void* d_out, int out_size)
{
    const float* hs = (const float*)d_in[0];
    const float* wq = (const float*)d_in[2];
    const float* bq = (const float*)d_in[3];
    const float* wk = (const float*)d_in[4];
    const float* bk = (const float*)d_in[5];
    const float* wv = (const float*)d_in[6];
    const float* bv = (const float*)d_in[7];
    const float* wo = (const float*)d_in[8];
    float* out = (float*)d_out;

    float *q, *k, *cosd, *sind;
    __half *qh, *kh, *vh, *ctx_h, *hs_h, *wq_h, *wk_h, *wv_h, *wo_h;
    cudaGetSymbolAddress((void**)&q,     g_q);
    cudaGetSymbolAddress((void**)&k,     g_k);
    cudaGetSymbolAddress((void**)&qh,    g_qh);
    cudaGetSymbolAddress((void**)&kh,    g_kh);
    cudaGetSymbolAddress((void**)&vh,    g_vh);
    cudaGetSymbolAddress((void**)&ctx_h, g_ctx_h);
    cudaGetSymbolAddress((void**)&hs_h,  g_hs_h);
    cudaGetSymbolAddress((void**)&wq_h,  g_wq_h);
    cudaGetSymbolAddress((void**)&wk_h,  g_wk_h);
    cudaGetSymbolAddress((void**)&wv_h,  g_wv_h);
    cudaGetSymbolAddress((void**)&wo_h,  g_wo_h);
    cudaGetSymbolAddress((void**)&cosd,  g_cos);
    cudaGetSymbolAddress((void**)&sind,  g_sin);

    // conversions needed by gemm_qkv, then rope tables
    cvt_half<<<SEQ * HID / 4 / 1024,   256>>>(hs, hs_h, SEQ * HID / 4);
    cvt_half<<<HID * HID / 4 / 1024,   256>>>(wq, wq_h, HID * HID / 4);
    cvt_half<<<KVDIM * HID / 4 / 1024, 256>>>(wk, wk_h, KVDIM * HID / 4);
    cvt_half<<<KVDIM * HID / 4 / 1024, 256>>>(wv, wv_h, KVDIM * HID / 4);
    rope_tables<<<(SEQ * 64) / 256, 256>>>(cosd, sind);

    cudaFuncSetAttribute(gemm_qkv, cudaFuncAttributeMaxDynamicSharedMemorySize, GEMM_SMEM_BYTES);
    cudaFuncSetAttribute(gemm_f16, cudaFuncAttributeMaxDynamicSharedMemorySize, GEMM_SMEM_BYTES);

    // fused Q/K/V projection (V written directly as fp16)
    gemm_qkv<<<dim3((HID + 2 * KVDIM) / 128, SEQ / 128), 256, GEMM_SMEM_BYTES>>>(
        hs_h, wq_h, wk_h, wv_h, bq, bk, bv, q, k, vh);

    // rope (vectorized; fp32 math, single rounding to half)
    rope_apply<<<(SEQ * NH  * 16) / 256, 256>>>(q, qh, cosd, sind, NH);
    rope_apply<<<(SEQ * NKV * 16) / 256, 256>>>(k, kh, cosd, sind, NKV);

    // wo conversion (only needed before final gemm)
    cvt_half<<<HID * HID / 4 / 1024, 256>>>(wo, wo_h, HID * HID / 4);

    // attention (FA2, in-register log2-domain softmax, LPT block order)
    cudaFuncSetAttribute(attn_f16, cudaFuncAttributeMaxDynamicSharedMemorySize, ATTN_SMEM_BYTES);
    attn_f16<<<(SEQ / 128) * NH, 256, ATTN_SMEM_BYTES>>>(qh, kh, vh, ctx_h);

    // output projection
    gemm_f16<<<dim3(HID / 128, SEQ / 128), 256, GEMM_SMEM_BYTES>>>(
        ctx_h, wo_h, nullptr, out, SEQ, HID, HID);
}